// round 6
// baseline (speedup 1.0000x reference)
#include <cuda_runtime.h>

#define FULL 0xFFFFFFFFu
#define NQ 9
#define NL 2

// Precomputed Rot matrices: [layer][qubit][u00r,u00i,u01r,u01i,u10r,u10i,u11r,u11i]
__device__ float g_rot[NL * NQ * 8];

__global__ void rot_precompute(const float* __restrict__ w) {
    int i = threadIdx.x;
    if (i >= NL * NQ) return;
    float phi = w[i * 3 + 0], theta = w[i * 3 + 1], omega = w[i * 3 + 2];
    float st, ct; sincosf(0.5f * theta, &st, &ct);
    float sp, cp; sincosf(0.5f * (phi + omega), &sp, &cp);
    float sm, cm; sincosf(0.5f * (phi - omega), &sm, &cm);
    // u00 = e^{-i(phi+omega)/2} * cos(theta/2)
    g_rot[i * 8 + 0] = cp * ct;  g_rot[i * 8 + 1] = -sp * ct;
    // u01 = -e^{+i(phi-omega)/2} * sin(theta/2)
    g_rot[i * 8 + 2] = -cm * st; g_rot[i * 8 + 3] = -sm * st;
    // u10 = e^{-i(phi-omega)/2} * sin(theta/2)
    g_rot[i * 8 + 4] = cm * st;  g_rot[i * 8 + 5] = -sm * st;
    // u11 = e^{+i(phi+omega)/2} * cos(theta/2)
    g_rot[i * 8 + 6] = cp * ct;  g_rot[i * 8 + 7] = sp * ct;
}

// Generic 1-qubit gate on qubit Q. Qubits 0..3 live in the per-lane index
// bits (local), qubits 4..8 live in the lane-id bits (cross-lane shuffles).
template <int Q>
__device__ __forceinline__ void gate1(float* sr, float* si,
                                      float u00r, float u00i, float u01r, float u01i,
                                      float u10r, float u10i, float u11r, float u11i,
                                      int lane) {
    if (Q < 4) {
#pragma unroll
        for (int t = 0; t < 8; t++) {
            const int j0 = ((t >> Q) << (Q + 1)) | (t & ((1 << Q) - 1));
            const int j1 = j0 | (1 << Q);
            float ar = sr[j0], ai = si[j0], br = sr[j1], bi = si[j1];
            sr[j0] = u00r * ar - u00i * ai + u01r * br - u01i * bi;
            si[j0] = u00r * ai + u00i * ar + u01r * bi + u01i * br;
            sr[j1] = u10r * ar - u10i * ai + u11r * br - u11i * bi;
            si[j1] = u10r * ai + u10i * ar + u11r * bi + u11i * br;
        }
    } else {
        const int m = 1 << (Q - 4);
        const bool hi = (lane & m) != 0;
        // out = va*mine + vb*partner  (va = hi? u11:u00, vb = hi? u10:u01)
        const float var = hi ? u11r : u00r, vai = hi ? u11i : u00i;
        const float vbr = hi ? u10r : u01r, vbi = hi ? u10i : u01i;
#pragma unroll
        for (int j = 0; j < 16; j++) {
            float pr = __shfl_xor_sync(FULL, sr[j], m);
            float pi = __shfl_xor_sync(FULL, si[j], m);
            float mr = sr[j], mi = si[j];
            sr[j] = var * mr - vai * mi + vbr * pr - vbi * pi;
            si[j] = var * mi + vai * mr + vbr * pi + vbi * pr;
        }
    }
}

// RX gate: u = [[c, -i s], [-i s, c]] — symmetric, so cross-lane form is uniform.
template <int Q>
__device__ __forceinline__ void gate_rx(float* sr, float* si, float c, float s) {
    if (Q < 4) {
#pragma unroll
        for (int t = 0; t < 8; t++) {
            const int j0 = ((t >> Q) << (Q + 1)) | (t & ((1 << Q) - 1));
            const int j1 = j0 | (1 << Q);
            float ar = sr[j0], ai = si[j0], br = sr[j1], bi = si[j1];
            sr[j0] = c * ar + s * bi;
            si[j0] = c * ai - s * br;
            sr[j1] = c * br + s * ai;
            si[j1] = c * bi - s * ar;
        }
    } else {
        const int m = 1 << (Q - 4);
#pragma unroll
        for (int j = 0; j < 16; j++) {
            float pr = __shfl_xor_sync(FULL, sr[j], m);
            float pi = __shfl_xor_sync(FULL, si[j], m);
            float mr = sr[j], mi = si[j];
            sr[j] = c * mr + s * pi;
            si[j] = c * mi - s * pr;
        }
    }
}

template <int C, int T>
__device__ __forceinline__ void cnot(float* sr, float* si, int lane) {
    if (C < 4 && T < 4) {
        // pure register permutation
#pragma unroll
        for (int t = 0; t < 4; t++) {
            int j = 0, tt = t;
#pragma unroll
            for (int b = 0; b < 4; b++) {
                if (b != C && b != T) { j |= (tt & 1) << b; tt >>= 1; }
            }
            const int j0 = j | (1 << C);
            const int j1 = j0 | (1 << T);
            float tr = sr[j0]; sr[j0] = sr[j1]; sr[j1] = tr;
            float ti = si[j0]; si[j0] = si[j1]; si[j1] = ti;
        }
    } else if (C < 4 && T >= 4) {
        const int m = 1 << (T - 4);
#pragma unroll
        for (int j = 0; j < 16; j++) {
            if (j & (1 << C)) {  // compile-time condition: all lanes agree
                sr[j] = __shfl_xor_sync(FULL, sr[j], m);
                si[j] = __shfl_xor_sync(FULL, si[j], m);
            }
        }
    } else if (C >= 4 && T < 4) {
        const bool cond = (lane >> (C - 4)) & 1;
#pragma unroll
        for (int j = 0; j < 16; j++) {
            if (!(j & (1 << T))) {
                const int j1 = j | (1 << T);
                float a = sr[j], b = sr[j1];
                sr[j]  = cond ? b : a;
                sr[j1] = cond ? a : b;
                a = si[j]; b = si[j1];
                si[j]  = cond ? b : a;
                si[j1] = cond ? a : b;
            }
        }
    } else {
        const int m = 1 << (T - 4);
        const bool cond = (lane >> (C - 4)) & 1;
#pragma unroll
        for (int j = 0; j < 16; j++) {
            float pr = __shfl_xor_sync(FULL, sr[j], m);
            float pi = __shfl_xor_sync(FULL, si[j], m);
            sr[j] = cond ? pr : sr[j];
            si[j] = cond ? pi : si[j];
        }
    }
}

__global__ void __launch_bounds__(256) qk_main(const float* __restrict__ x,
                                               float* __restrict__ out, int n_patch) {
    const int warp = (blockIdx.x * blockDim.x + threadIdx.x) >> 5;
    const int lane = threadIdx.x & 31;
    if (warp >= n_patch) return;

    // patch -> (b, h, w), H = W = 64
    const int b = warp >> 12;
    const int h = (warp >> 6) & 63;
    const int w = warp & 63;

    // lanes 0..8 each load one embedding angle (3x3 neighborhood, zero padded)
    float ang = 0.0f;
    if (lane < 9) {
        const int kh = lane / 3, kw = lane % 3;
        const int hh = h - 1 + kh, ww = w - 1 + kw;
        if (hh >= 0 && hh < 64 && ww >= 0 && ww < 64)
            ang = x[(b << 12) + (hh << 6) + ww];
    }

    // state |0...0>: amplitude index = (lane << 4) | j ; qubit q <-> bit q
    float sr[16], si[16];
#pragma unroll
    for (int j = 0; j < 16; j++) { sr[j] = 0.0f; si[j] = 0.0f; }
    if (lane == 0) sr[0] = 1.0f;

    // ---- AngleEmbedding: RX(angle_q) on each qubit ----
#define APPLY_RX(Q)                                                   \
    {                                                                 \
        float a = __shfl_sync(FULL, ang, Q);                          \
        float s_, c_;                                                 \
        __sincosf(0.5f * a, &s_, &c_);                                \
        gate_rx<Q>(sr, si, c_, s_);                                   \
    }
    APPLY_RX(0) APPLY_RX(1) APPLY_RX(2) APPLY_RX(3) APPLY_RX(4)
    APPLY_RX(5) APPLY_RX(6) APPLY_RX(7) APPLY_RX(8)
#undef APPLY_RX

#define APPLY_ROT(L, Q)                                               \
    {                                                                 \
        const float* u = &g_rot[((L) * NQ + (Q)) * 8];                \
        gate1<Q>(sr, si, u[0], u[1], u[2], u[3],                      \
                 u[4], u[5], u[6], u[7], lane);                       \
    }

    // ---- Layer 0: Rot on each qubit, then CNOT ring r=1 ----
    APPLY_ROT(0, 0) APPLY_ROT(0, 1) APPLY_ROT(0, 2) APPLY_ROT(0, 3)
    APPLY_ROT(0, 4) APPLY_ROT(0, 5) APPLY_ROT(0, 6) APPLY_ROT(0, 7)
    APPLY_ROT(0, 8)
    cnot<0, 1>(sr, si, lane); cnot<1, 2>(sr, si, lane); cnot<2, 3>(sr, si, lane);
    cnot<3, 4>(sr, si, lane); cnot<4, 5>(sr, si, lane); cnot<5, 6>(sr, si, lane);
    cnot<6, 7>(sr, si, lane); cnot<7, 8>(sr, si, lane); cnot<8, 0>(sr, si, lane);

    // ---- Layer 1: Rot on each qubit, then CNOT ring r=2 ----
    APPLY_ROT(1, 0) APPLY_ROT(1, 1) APPLY_ROT(1, 2) APPLY_ROT(1, 3)
    APPLY_ROT(1, 4) APPLY_ROT(1, 5) APPLY_ROT(1, 6) APPLY_ROT(1, 7)
    APPLY_ROT(1, 8)
    cnot<0, 2>(sr, si, lane); cnot<1, 3>(sr, si, lane); cnot<2, 4>(sr, si, lane);
    cnot<3, 5>(sr, si, lane); cnot<4, 6>(sr, si, lane); cnot<5, 7>(sr, si, lane);
    cnot<6, 8>(sr, si, lane); cnot<7, 0>(sr, si, lane); cnot<8, 1>(sr, si, lane);
#undef APPLY_ROT

    // ---- <Z_0>: qubit 0 is local index bit 0 ----
    float z = 0.0f;
#pragma unroll
    for (int j = 0; j < 16; j++) {
        float p = sr[j] * sr[j] + si[j] * si[j];
        z += (j & 1) ? -p : p;
    }
#pragma unroll
    for (int o = 16; o > 0; o >>= 1) z += __shfl_xor_sync(FULL, z, o);

    if (lane == 0) out[warp] = z;
}

extern "C" void kernel_launch(void* const* d_in, const int* in_sizes, int n_in,
                              void* d_out, int out_size) {
    const float* x;
    const float* wts;
    // metadata order: x (32768 floats), weights (54 floats). Be defensive.
    if (n_in >= 2 && in_sizes[0] == NL * NQ * 3) {
        wts = (const float*)d_in[0];
        x = (const float*)d_in[1];
    } else {
        x = (const float*)d_in[0];
        wts = (const float*)d_in[1];
    }

    rot_precompute<<<1, 32>>>(wts);

    const int n_patch = out_size;          // 8*1*64*64 = 32768
    const int warps_per_block = 256 / 32;  // 8
    const int blocks = (n_patch + warps_per_block - 1) / warps_per_block;
    qk_main<<<blocks, 256>>>(x, (float*)d_out, n_patch);
}

// round 7
// speedup vs baseline: 1.0035x; 1.0035x over previous
#include <cuda_runtime.h>

#define FULL 0xFFFFFFFFu
#define NQ 9
#define NL 2

// Precomputed Rot matrices: [layer][qubit][u00r,u00i,u01r,u01i,u10r,u10i,u11r,u11i]
__device__ float g_rot[NL * NQ * 8];

__global__ void rot_precompute(const float* __restrict__ w) {
    int i = threadIdx.x;
    if (i >= NL * NQ) return;
    float phi = w[i * 3 + 0], theta = w[i * 3 + 1], omega = w[i * 3 + 2];
    float st, ct; sincosf(0.5f * theta, &st, &ct);
    float sp, cp; sincosf(0.5f * (phi + omega), &sp, &cp);
    float sm, cm; sincosf(0.5f * (phi - omega), &sm, &cm);
    // u00 = e^{-i(phi+omega)/2} * cos(theta/2)
    g_rot[i * 8 + 0] = cp * ct;  g_rot[i * 8 + 1] = -sp * ct;
    // u01 = -e^{+i(phi-omega)/2} * sin(theta/2)
    g_rot[i * 8 + 2] = -cm * st; g_rot[i * 8 + 3] = -sm * st;
    // u10 = e^{-i(phi-omega)/2} * sin(theta/2)
    g_rot[i * 8 + 4] = cm * st;  g_rot[i * 8 + 5] = -sm * st;
    // u11 = e^{+i(phi+omega)/2} * cos(theta/2)
    g_rot[i * 8 + 6] = cp * ct;  g_rot[i * 8 + 7] = sp * ct;
}

// Generic 1-qubit gate on qubit Q. Qubits 0..3 live in the per-lane index
// bits (local), qubits 4..8 live in the lane-id bits (cross-lane shuffles).
template <int Q>
__device__ __forceinline__ void gate1(float* sr, float* si,
                                      float u00r, float u00i, float u01r, float u01i,
                                      float u10r, float u10i, float u11r, float u11i,
                                      int lane) {
    if (Q < 4) {
#pragma unroll
        for (int t = 0; t < 8; t++) {
            const int j0 = ((t >> Q) << (Q + 1)) | (t & ((1 << Q) - 1));
            const int j1 = j0 | (1 << Q);
            float ar = sr[j0], ai = si[j0], br = sr[j1], bi = si[j1];
            sr[j0] = u00r * ar - u00i * ai + u01r * br - u01i * bi;
            si[j0] = u00r * ai + u00i * ar + u01r * bi + u01i * br;
            sr[j1] = u10r * ar - u10i * ai + u11r * br - u11i * bi;
            si[j1] = u10r * ai + u10i * ar + u11r * bi + u11i * br;
        }
    } else {
        const int m = 1 << (Q - 4);
        const bool hi = (lane & m) != 0;
        // out = va*mine + vb*partner  (va = hi? u11:u00, vb = hi? u10:u01)
        const float var = hi ? u11r : u00r, vai = hi ? u11i : u00i;
        const float vbr = hi ? u10r : u01r, vbi = hi ? u10i : u01i;
#pragma unroll
        for (int j = 0; j < 16; j++) {
            float pr = __shfl_xor_sync(FULL, sr[j], m);
            float pi = __shfl_xor_sync(FULL, si[j], m);
            float mr = sr[j], mi = si[j];
            sr[j] = var * mr - vai * mi + vbr * pr - vbi * pi;
            si[j] = var * mi + vai * mr + vbr * pi + vbi * pr;
        }
    }
}

// RX gate: u = [[c, -i s], [-i s, c]] — symmetric, so cross-lane form is uniform.
template <int Q>
__device__ __forceinline__ void gate_rx(float* sr, float* si, float c, float s) {
    if (Q < 4) {
#pragma unroll
        for (int t = 0; t < 8; t++) {
            const int j0 = ((t >> Q) << (Q + 1)) | (t & ((1 << Q) - 1));
            const int j1 = j0 | (1 << Q);
            float ar = sr[j0], ai = si[j0], br = sr[j1], bi = si[j1];
            sr[j0] = c * ar + s * bi;
            si[j0] = c * ai - s * br;
            sr[j1] = c * br + s * ai;
            si[j1] = c * bi - s * ar;
        }
    } else {
        const int m = 1 << (Q - 4);
#pragma unroll
        for (int j = 0; j < 16; j++) {
            float pr = __shfl_xor_sync(FULL, sr[j], m);
            float pi = __shfl_xor_sync(FULL, si[j], m);
            float mr = sr[j], mi = si[j];
            sr[j] = c * mr + s * pi;
            si[j] = c * mi - s * pr;
        }
    }
}

template <int C, int T>
__device__ __forceinline__ void cnot(float* sr, float* si, int lane) {
    if (C < 4 && T < 4) {
        // pure register permutation
#pragma unroll
        for (int t = 0; t < 4; t++) {
            int j = 0, tt = t;
#pragma unroll
            for (int b = 0; b < 4; b++) {
                if (b != C && b != T) { j |= (tt & 1) << b; tt >>= 1; }
            }
            const int j0 = j | (1 << C);
            const int j1 = j0 | (1 << T);
            float tr = sr[j0]; sr[j0] = sr[j1]; sr[j1] = tr;
            float ti = si[j0]; si[j0] = si[j1]; si[j1] = ti;
        }
    } else if (C < 4 && T >= 4) {
        const int m = 1 << (T - 4);
#pragma unroll
        for (int j = 0; j < 16; j++) {
            if (j & (1 << C)) {  // compile-time condition: all lanes agree
                sr[j] = __shfl_xor_sync(FULL, sr[j], m);
                si[j] = __shfl_xor_sync(FULL, si[j], m);
            }
        }
    } else if (C >= 4 && T < 4) {
        const bool cond = (lane >> (C - 4)) & 1;
#pragma unroll
        for (int j = 0; j < 16; j++) {
            if (!(j & (1 << T))) {
                const int j1 = j | (1 << T);
                float a = sr[j], b = sr[j1];
                sr[j]  = cond ? b : a;
                sr[j1] = cond ? a : b;
                a = si[j]; b = si[j1];
                si[j]  = cond ? b : a;
                si[j1] = cond ? a : b;
            }
        }
    } else {
        const int m = 1 << (T - 4);
        const bool cond = (lane >> (C - 4)) & 1;
#pragma unroll
        for (int j = 0; j < 16; j++) {
            float pr = __shfl_xor_sync(FULL, sr[j], m);
            float pi = __shfl_xor_sync(FULL, si[j], m);
            sr[j] = cond ? pr : sr[j];
            si[j] = cond ? pi : si[j];
        }
    }
}

__global__ void __launch_bounds__(256) qk_main(const float* __restrict__ x,
                                               float* __restrict__ out, int n_patch) {
    const int warp = (blockIdx.x * blockDim.x + threadIdx.x) >> 5;
    const int lane = threadIdx.x & 31;
    if (warp >= n_patch) return;

    // patch -> (b, h, w), H = W = 64
    const int b = warp >> 12;
    const int h = (warp >> 6) & 63;
    const int w = warp & 63;

    // lanes 0..8 each load one embedding angle (3x3 neighborhood, zero padded)
    float ang = 0.0f;
    if (lane < 9) {
        const int kh = lane / 3, kw = lane % 3;
        const int hh = h - 1 + kh, ww = w - 1 + kw;
        if (hh >= 0 && hh < 64 && ww >= 0 && ww < 64)
            ang = x[(b << 12) + (hh << 6) + ww];
    }

    // state |0...0>: amplitude index = (lane << 4) | j ; qubit q <-> bit q
    float sr[16], si[16];
#pragma unroll
    for (int j = 0; j < 16; j++) { sr[j] = 0.0f; si[j] = 0.0f; }
    if (lane == 0) sr[0] = 1.0f;

    // ---- AngleEmbedding: RX(angle_q) on each qubit ----
#define APPLY_RX(Q)                                                   \
    {                                                                 \
        float a = __shfl_sync(FULL, ang, Q);                          \
        float s_, c_;                                                 \
        __sincosf(0.5f * a, &s_, &c_);                                \
        gate_rx<Q>(sr, si, c_, s_);                                   \
    }
    APPLY_RX(0) APPLY_RX(1) APPLY_RX(2) APPLY_RX(3) APPLY_RX(4)
    APPLY_RX(5) APPLY_RX(6) APPLY_RX(7) APPLY_RX(8)
#undef APPLY_RX

#define APPLY_ROT(L, Q)                                               \
    {                                                                 \
        const float* u = &g_rot[((L) * NQ + (Q)) * 8];                \
        gate1<Q>(sr, si, u[0], u[1], u[2], u[3],                      \
                 u[4], u[5], u[6], u[7], lane);                       \
    }

    // ---- Layer 0: Rot on each qubit, then CNOT ring r=1 ----
    APPLY_ROT(0, 0) APPLY_ROT(0, 1) APPLY_ROT(0, 2) APPLY_ROT(0, 3)
    APPLY_ROT(0, 4) APPLY_ROT(0, 5) APPLY_ROT(0, 6) APPLY_ROT(0, 7)
    APPLY_ROT(0, 8)
    cnot<0, 1>(sr, si, lane); cnot<1, 2>(sr, si, lane); cnot<2, 3>(sr, si, lane);
    cnot<3, 4>(sr, si, lane); cnot<4, 5>(sr, si, lane); cnot<5, 6>(sr, si, lane);
    cnot<6, 7>(sr, si, lane); cnot<7, 8>(sr, si, lane); cnot<8, 0>(sr, si, lane);

    // ---- Layer 1: Rot on each qubit, then CNOT ring r=2 ----
    APPLY_ROT(1, 0) APPLY_ROT(1, 1) APPLY_ROT(1, 2) APPLY_ROT(1, 3)
    APPLY_ROT(1, 4) APPLY_ROT(1, 5) APPLY_ROT(1, 6) APPLY_ROT(1, 7)
    APPLY_ROT(1, 8)
    cnot<0, 2>(sr, si, lane); cnot<1, 3>(sr, si, lane); cnot<2, 4>(sr, si, lane);
    cnot<3, 5>(sr, si, lane); cnot<4, 6>(sr, si, lane); cnot<5, 7>(sr, si, lane);
    cnot<6, 8>(sr, si, lane); cnot<7, 0>(sr, si, lane); cnot<8, 1>(sr, si, lane);
#undef APPLY_ROT

    // ---- <Z_0>: qubit 0 is local index bit 0 ----
    float z = 0.0f;
#pragma unroll
    for (int j = 0; j < 16; j++) {
        float p = sr[j] * sr[j] + si[j] * si[j];
        z += (j & 1) ? -p : p;
    }
#pragma unroll
    for (int o = 16; o > 0; o >>= 1) z += __shfl_xor_sync(FULL, z, o);

    if (lane == 0) out[warp] = z;
}

extern "C" void kernel_launch(void* const* d_in, const int* in_sizes, int n_in,
                              void* d_out, int out_size) {
    const float* x;
    const float* wts;
    // metadata order: x (32768 floats), weights (54 floats). Be defensive.
    if (n_in >= 2 && in_sizes[0] == NL * NQ * 3) {
        wts = (const float*)d_in[0];
        x = (const float*)d_in[1];
    } else {
        x = (const float*)d_in[0];
        wts = (const float*)d_in[1];
    }

    rot_precompute<<<1, 32>>>(wts);

    const int n_patch = out_size;          // 8*1*64*64 = 32768
    const int warps_per_block = 256 / 32;  // 8
    const int blocks = (n_patch + warps_per_block - 1) / warps_per_block;
    qk_main<<<blocks, 256>>>(x, (float*)d_out, n_patch);
}